// round 2
// baseline (speedup 1.0000x reference)
#include <cuda_runtime.h>
#include <math.h>

// Problem constants: b=2, nc=64, H=W=64
#define Bz 2
#define NC 64
#define Hh 64
#define Ww 64
#define Ls 4096          // H*W
#define KD 576           // nc * 3 * 3
#define EPSF 1e-7f

// Scratch (worst-case cnt == Ls; actual data gives cnt ~ 8 per sample)
__device__ int   g_cnt[Bz];
__device__ int   g_list[Bz][Ls];
__device__ float g_K[Bz][Ls][KD];     // normalized bg patch rows (candidates only)
__device__ float g_corr[Bz][Ls][Ls];  // corr rows   (candidates only)
__device__ float g_sc[Bz][Ls][Ls];    // score rows  (candidates only)

// ---------------------------------------------------------------------------
// K1: per-sample, ONE block of 1024 threads: compute mm[l], single-pass block
// scan, compact candidate l's in ascending order (deterministic tie-break).
// ---------------------------------------------------------------------------
__global__ void k_scan(const float* __restrict__ mask) {
    int b = blockIdx.x;
    const float* m = mask + b * Ls;
    int tid = threadIdx.x;              // 0..1023
    int lane = tid & 31, warp = tid >> 5;
    __shared__ int wsum[32];

    int ok[4];
    int myc = 0;
    #pragma unroll
    for (int j = 0; j < 4; j++) {
        int l = tid * 4 + j;
        int y = l >> 6, x = l & 63;
        int o = 1;
        #pragma unroll
        for (int dy = -1; dy <= 1; dy++) {
            int yy = y + dy;
            if (yy < 0 || yy >= Hh) continue;
            #pragma unroll
            for (int dx = -1; dx <= 1; dx++) {
                int xx = x + dx;
                if (xx >= 0 && xx < Ww && m[yy * Ww + xx] != 0.0f) o = 0;
            }
        }
        ok[j] = o; myc += o;
    }
    // inclusive warp scan
    int v = myc;
    #pragma unroll
    for (int off = 1; off < 32; off <<= 1) {
        int t = __shfl_up_sync(0xffffffffu, v, off);
        if (lane >= off) v += t;
    }
    if (lane == 31) wsum[warp] = v;
    __syncthreads();
    if (warp == 0) {
        int t = wsum[lane];
        #pragma unroll
        for (int off = 1; off < 32; off <<= 1) {
            int u = __shfl_up_sync(0xffffffffu, t, off);
            if (lane >= off) t += u;
        }
        wsum[lane] = t;
    }
    __syncthreads();
    int excl = (v - myc) + (warp > 0 ? wsum[warp - 1] : 0);
    #pragma unroll
    for (int j = 0; j < 4; j++) {
        if (ok[j]) g_list[b][excl++] = tid * 4 + j;
    }
    if (tid == 0) g_cnt[b] = wsum[31];
}

// ---------------------------------------------------------------------------
// K2: build normalized kernel rows for candidates.
// ---------------------------------------------------------------------------
__global__ void k_build(const float* __restrict__ bgin, const float* __restrict__ mask) {
    int b = blockIdx.y;
    int cnt = g_cnt[b];
    int tid = threadIdx.x;
    __shared__ float sval[KD];
    __shared__ float ssum[256];
    for (int i = blockIdx.x; i < cnt; i += gridDim.x) {
        int l = g_list[b][i];
        int y = l >> 6, x = l & 63;
        float acc = 0.f;
        for (int k = tid; k < KD; k += 256) {
            int c = k / 9, pp = k % 9;
            int ph = pp / 3, pw = pp % 3;
            int yy = y + ph - 1, xx = x + pw - 1;
            float v = 0.f;
            if (yy >= 0 && yy < Hh && xx >= 0 && xx < Ww) {
                float mv = mask[b * Ls + yy * Ww + xx];
                v = bgin[(b * NC + c) * Ls + yy * Ww + xx] * (1.f - mv);
            }
            v += EPSF;
            sval[k] = v;
            acc += v * v;
        }
        ssum[tid] = acc;
        __syncthreads();
        for (int off = 128; off > 0; off >>= 1) {
            if (tid < off) ssum[tid] += ssum[tid + off];
            __syncthreads();
        }
        float norm = sqrtf(ssum[0]);
        for (int k = tid; k < KD; k += 256) g_K[b][i][k] = sval[k] / norm;
        __syncthreads();
    }
}

// ---------------------------------------------------------------------------
// K3: corr[i][s] = <K_i, fg patch at s> (zero-padded fg)
// ---------------------------------------------------------------------------
__global__ void k_corr(const float* __restrict__ fgin) {
    int b = blockIdx.z;
    int cnt = g_cnt[b];
    int tid = threadIdx.x;
    int s = blockIdx.x * 256 + tid;
    int y = s >> 6, x = s & 63;
    const float* fg = fgin + b * NC * Ls;
    __shared__ float sk[KD];
    for (int i = blockIdx.y; i < cnt; i += gridDim.y) {
        for (int k = tid; k < KD; k += 256) sk[k] = g_K[b][i][k];
        __syncthreads();
        float acc = 0.f;
        for (int c = 0; c < NC; c++) {
            const float* fc = fg + c * Ls;
            const float* kc = sk + c * 9;
            #pragma unroll
            for (int ph = 0; ph < 3; ph++) {
                int yy = y + ph - 1;
                if (yy < 0 || yy >= Hh) continue;
                const float* fr = fc + yy * Ww;
                #pragma unroll
                for (int pw = 0; pw < 3; pw++) {
                    int xx = x + pw - 1;
                    if (xx >= 0 && xx < Ww) acc += kc[ph * 3 + pw] * fr[xx];
                }
            }
        }
        g_corr[b][i][s] = acc;
        __syncthreads();
    }
}

// ---------------------------------------------------------------------------
// K4: per spatial s: v_i = 10 * boxsum(corr_i) via shared-memory separable
// box filter; softmax over full l-axis (masked rows contribute exp(-vmax)
// each, closed-form); scores to g_sc; argmax -> flow.
// Block: 128 threads = 2 spatial rows. Grid: (32, Bz).
// ---------------------------------------------------------------------------
__global__ void k_soft(float* __restrict__ flowout) {
    int b = blockIdx.y;
    int cnt = g_cnt[b];
    int tid = threadIdx.x;               // 0..127
    int r0 = blockIdx.x * 2;             // first spatial row of this block
    int q = tid >> 6, x = tid & 63;
    int y = r0 + q;
    int s = y * Ww + x;

    __shared__ float raw[4][64];         // corr rows r0-1 .. r0+2 (0 outside)
    __shared__ float hs[4][64];          // horizontal 3-sums
    __shared__ float vsh[32][128];       // per-thread v cache (fast path)

    bool fast = (cnt <= 32);
    float vmax = (cnt < Ls) ? 0.f : -INFINITY;

    for (int i = 0; i < cnt; i++) {
        for (int t = tid; t < 256; t += 128) {
            int j = t >> 6, xx = t & 63;
            int gr = r0 - 1 + j;
            raw[j][xx] = (gr >= 0 && gr < Hh) ? g_corr[b][i][gr * Ww + xx] : 0.f;
        }
        __syncthreads();
        for (int t = tid; t < 256; t += 128) {
            int j = t >> 6, xx = t & 63;
            float a = raw[j][xx];
            if (xx > 0)  a += raw[j][xx - 1];
            if (xx < 63) a += raw[j][xx + 1];
            hs[j][xx] = a;
        }
        __syncthreads();
        float v = 10.f * (hs[q][x] + hs[q + 1][x] + hs[q + 2][x]);
        vmax = fmaxf(vmax, v);
        if (fast) vsh[i][tid] = v;
        else      g_sc[b][i][s] = v;
        __syncthreads();                 // raw/hs reuse next iteration
    }

    float denom = (cnt < Ls) ? (float)(Ls - cnt) * expf(-vmax) : 0.f;
    float bestv = -INFINITY;
    int bestl = 0;
    for (int i = 0; i < cnt; i++) {
        float v = fast ? vsh[i][tid] : g_sc[b][i][s];
        float e = expf(v - vmax);
        denom += e;
        if (v > bestv) { bestv = v; bestl = g_list[b][i]; }  // ascending -> first-max
        if (fast) vsh[i][tid] = e;
        else      g_sc[b][i][s] = e;
    }
    float inv = 1.f / denom;
    for (int i = 0; i < cnt; i++) {
        float e = fast ? vsh[i][tid] : g_sc[b][i][s];
        g_sc[b][i][s] = e * inv;
    }

    flowout[(b * 2 + 0) * Ls + s] = (float)(bestl >> 6) - (float)y;
    flowout[(b * 2 + 1) * Ls + s] = (float)(bestl & 63) - (float)x;
}

// ---------------------------------------------------------------------------
// K5: rec[c,y,x] = sum_{ph,pw} sum_i scores[i, (y+1-ph, x+1-pw)] * K[i, c*9+pp]
// Candidate kernels staged in shared in chunks of 16 (coalesced load;
// LDS index c*9+pp is bank-conflict-free since gcd(9,32)=1).
// final = (rec*m/9)*m + fg*(1-m)
// ---------------------------------------------------------------------------
__global__ void k_rec(const float* __restrict__ fgin, const float* __restrict__ mask,
                      float* __restrict__ att) {
    int b = blockIdx.y;
    int cnt = g_cnt[b];
    int tid = threadIdx.x;               // 256
    int s = blockIdx.x * 4 + (tid >> 6);
    int c = tid & 63;
    int y = s >> 6, x = s & 63;

    __shared__ float sk[16][KD];         // 36 KB

    float acc = 0.f;
    for (int c0 = 0; c0 < cnt; c0 += 16) {
        int nchunk = min(16, cnt - c0);
        const float* src = &g_K[b][c0][0];
        for (int t = tid; t < nchunk * KD; t += 256)
            ((float*)sk)[t] = src[t];
        __syncthreads();
        for (int i = 0; i < nchunk; i++) {
            const float* ki = &sk[i][c * 9];
            const float* sc = &g_sc[b][c0 + i][0];
            #pragma unroll
            for (int ph = 0; ph < 3; ph++) {
                int yy = y + 1 - ph;
                if (yy < 0 || yy >= Hh) continue;
                #pragma unroll
                for (int pw = 0; pw < 3; pw++) {
                    int xx = x + 1 - pw;
                    if (xx < 0 || xx >= Ww) continue;
                    acc += sc[yy * Ww + xx] * ki[ph * 3 + pw];
                }
            }
        }
        __syncthreads();
    }
    float mv = mask[b * Ls + s];
    float fgv = fgin[(b * NC + c) * Ls + s];
    float rec = (acc * mv) / 9.f;
    att[(b * NC + c) * Ls + s] = rec * mv + fgv * (1.f - mv);
}

// ---------------------------------------------------------------------------
extern "C" void kernel_launch(void* const* d_in, const int* in_sizes, int n_in,
                              void* d_out, int out_size) {
    const float* fg   = (const float*)d_in[0];   // foreground [2,64,64,64]
    const float* bg   = (const float*)d_in[1];   // background [2,64,64,64]
    const float* mask = (const float*)d_in[2];   // mask       [2,1,64,64]
    float* att  = (float*)d_out;                 // attended   [2,64,64,64]
    float* flow = (float*)d_out + Bz * NC * Ls;  // flow       [2,2,64,64]

    k_scan<<<Bz, 1024>>>(mask);
    k_build<<<dim3(64, Bz), 256>>>(bg, mask);
    k_corr<<<dim3(16, 64, Bz), 256>>>(fg);
    k_soft<<<dim3(32, Bz), 128>>>(flow);
    k_rec<<<dim3(1024, Bz), 256>>>(fg, mask, att);
}

// round 3
// speedup vs baseline: 1.2019x; 1.2019x over previous
#include <cuda_runtime.h>
#include <math.h>

// Problem constants: b=2, nc=64, H=W=64
#define Bz 2
#define NC 64
#define Hh 64
#define Ww 64
#define Ls 4096          // H*W
#define KD 576           // nc * 3 * 3
#define EPSF 1e-7f
#define MAXC 24          // fast-path candidate capacity in k_soft
#define RCH 12           // k_rec chunk

// Scratch (worst-case cnt == Ls; actual data gives cnt ~ 12 per sample)
__device__ int   g_cnt[Bz];
__device__ int   g_list[Bz][Ls];
__device__ float g_K[Bz][Ls][KD];     // normalized bg patch rows (candidates only)
__device__ float g_corr[Bz][Ls][Ls];  // corr rows   (candidates only)
__device__ float g_sc[Bz][Ls][Ls];    // score rows  (candidates only)

// ---------------------------------------------------------------------------
// K1: per-sample, ONE 1024-thread block. Phase A: mm[l] + block scan ->
// ordered candidate list (smem + mirrored to global). Phase B: build
// normalized kernel rows, 16 candidates in parallel (64 threads each).
// ---------------------------------------------------------------------------
__global__ void k_scanbuild(const float* __restrict__ mask,
                            const float* __restrict__ bgin) {
    int b = blockIdx.x;
    const float* m = mask + b * Ls;
    int tid = threadIdx.x, lane = tid & 31, warp = tid >> 5;
    __shared__ int   wsum[32];
    __shared__ int   s_list[Ls];      // 16KB
    __shared__ int   s_cnt;
    __shared__ float s_norm[32];

    // ---- Phase A: mm + single-pass scan (4 cells/thread) ----
    int ok[4]; int myc = 0;
    #pragma unroll
    for (int j = 0; j < 4; j++) {
        int l = tid * 4 + j;
        int y = l >> 6, x = l & 63;
        int o = 1;
        #pragma unroll
        for (int dy = -1; dy <= 1; dy++) {
            int yy = y + dy;
            if (yy < 0 || yy >= Hh) continue;
            #pragma unroll
            for (int dx = -1; dx <= 1; dx++) {
                int xx = x + dx;
                if (xx >= 0 && xx < Ww && m[yy * Ww + xx] != 0.0f) o = 0;
            }
        }
        ok[j] = o; myc += o;
    }
    int v = myc;
    #pragma unroll
    for (int off = 1; off < 32; off <<= 1) {
        int t = __shfl_up_sync(0xffffffffu, v, off);
        if (lane >= off) v += t;
    }
    if (lane == 31) wsum[warp] = v;
    __syncthreads();
    if (warp == 0) {
        int t = wsum[lane];
        #pragma unroll
        for (int off = 1; off < 32; off <<= 1) {
            int u = __shfl_up_sync(0xffffffffu, t, off);
            if (lane >= off) t += u;
        }
        wsum[lane] = t;
    }
    __syncthreads();
    int excl = (v - myc) + (warp > 0 ? wsum[warp - 1] : 0);
    #pragma unroll
    for (int j = 0; j < 4; j++)
        if (ok[j]) s_list[excl++] = tid * 4 + j;
    if (tid == 0) { s_cnt = wsum[31]; g_cnt[b] = wsum[31]; }
    __syncthreads();
    int cnt = s_cnt;
    for (int t = tid; t < cnt; t += 1024) g_list[b][t] = s_list[t];

    // ---- Phase B: build normalized kernels, 16 candidates at a time ----
    int grp = tid >> 6;     // 0..15
    int c   = tid & 63;     // channel
    for (int i0 = 0; i0 < cnt; i0 += 16) {
        int i = i0 + grp;
        bool act = (i < cnt);
        int l = act ? s_list[i] : 0;
        int y = l >> 6, x = l & 63;
        float pv[9]; float ss = 0.f;
        #pragma unroll
        for (int pp = 0; pp < 9; pp++) {
            int ph = pp / 3, pw = pp % 3;
            int yy = y + ph - 1, xx = x + pw - 1;
            float t = 0.f;
            if (yy >= 0 && yy < Hh && xx >= 0 && xx < Ww)
                t = bgin[(b * NC + c) * Ls + yy * Ww + xx] * (1.f - m[yy * Ww + xx]);
            t += EPSF;
            pv[pp] = t; ss += t * t;
        }
        #pragma unroll
        for (int o = 16; o > 0; o >>= 1) ss += __shfl_xor_sync(0xffffffffu, ss, o);
        if (lane == 0) s_norm[warp] = ss;
        __syncthreads();
        float norm = sqrtf(s_norm[grp * 2] + s_norm[grp * 2 + 1]);
        if (act) {
            #pragma unroll
            for (int pp = 0; pp < 9; pp++)
                g_K[b][i][c * 9 + pp] = pv[pp] / norm;
        }
        __syncthreads();
    }
}

// ---------------------------------------------------------------------------
// K2: corr[i][s] = <K_i, fg patch at s> (zero-padded fg)
// ---------------------------------------------------------------------------
__global__ void k_corr(const float* __restrict__ fgin) {
    int b = blockIdx.z;
    int cnt = g_cnt[b];
    int tid = threadIdx.x;
    int s = blockIdx.x * 256 + tid;
    int y = s >> 6, x = s & 63;
    const float* fg = fgin + b * NC * Ls;
    __shared__ float sk[KD];
    for (int i = blockIdx.y; i < cnt; i += gridDim.y) {
        for (int k = tid; k < KD; k += 256) sk[k] = g_K[b][i][k];
        __syncthreads();
        float acc = 0.f;
        #pragma unroll 4
        for (int c = 0; c < NC; c++) {
            const float* fc = fg + c * Ls;
            const float* kc = sk + c * 9;
            #pragma unroll
            for (int ph = 0; ph < 3; ph++) {
                int yy = y + ph - 1;
                if (yy < 0 || yy >= Hh) continue;
                const float* fr = fc + yy * Ww;
                #pragma unroll
                for (int pw = 0; pw < 3; pw++) {
                    int xx = x + pw - 1;
                    if (xx >= 0 && xx < Ww) acc += kc[ph * 3 + pw] * fr[xx];
                }
            }
        }
        g_corr[b][i][s] = acc;
        __syncthreads();
    }
}

// 3x3 spatial box-sum of a global corr row (zero outside grid) — slow path
__device__ __forceinline__ float boxsum_g(const float* __restrict__ row, int y, int x) {
    float a = 0.f;
    #pragma unroll
    for (int dy = -1; dy <= 1; dy++) {
        int yy = y + dy;
        if (yy < 0 || yy >= Hh) continue;
        const float* r = row + yy * Ww;
        #pragma unroll
        for (int dx = -1; dx <= 1; dx++) {
            int xx = x + dx;
            if (xx >= 0 && xx < Ww) a += r[xx];
        }
    }
    return a;
}

// ---------------------------------------------------------------------------
// K4: per spatial s: v_i = 10 * boxsum(corr_i); softmax over full l-axis
// (masked rows contribute exp(-vmax) each, closed-form); scores; argmax->flow.
// Fast path (cnt<=MAXC): ONE MLP burst loads every candidate's 4 corr rows
// into shared, one sync, then all compute from smem (no per-cand syncs).
// Block: 128 threads = 2 spatial rows. Grid: (32, Bz).
// ---------------------------------------------------------------------------
__global__ void k_soft(float* __restrict__ flowout) {
    int b = blockIdx.y;
    int cnt = g_cnt[b];
    int tid = threadIdx.x;               // 0..127
    int r0 = blockIdx.x * 2;
    int q = tid >> 6, x = tid & 63;
    int y = r0 + q;
    int s = y * Ww + x;

    __shared__ float raw[MAXC][4][64];   // 24KB
    __shared__ float esm[MAXC][128];     // 12KB
    __shared__ int   sl[MAXC];

    if (cnt <= MAXC) {
        // preload all candidate rows, back-to-back LDGs (high MLP)
        for (int i = 0; i < cnt; i++) {
            #pragma unroll
            for (int t2 = 0; t2 < 2; t2++) {
                int t = tid + t2 * 128;
                int j = t >> 6, xx = t & 63;
                int gr = r0 - 1 + j;
                raw[i][j][xx] = (gr >= 0 && gr < Hh) ? g_corr[b][i][gr * Ww + xx] : 0.f;
            }
        }
        if (tid < cnt) sl[tid] = g_list[b][tid];
        __syncthreads();

        float vmax = (cnt < Ls) ? 0.f : -INFINITY;
        for (int i = 0; i < cnt; i++) {
            float a = 0.f;
            #pragma unroll
            for (int dy = 0; dy < 3; dy++) {
                #pragma unroll
                for (int dx = -1; dx <= 1; dx++) {
                    int xx = x + dx;
                    if (xx >= 0 && xx < 64) a += raw[i][q + dy][xx];
                }
            }
            float vv = 10.f * a;
            esm[i][tid] = vv;
            vmax = fmaxf(vmax, vv);
        }
        float denom = (cnt < Ls) ? (float)(Ls - cnt) * expf(-vmax) : 0.f;
        float bestv = -INFINITY; int bestl = 0;
        for (int i = 0; i < cnt; i++) {
            float vv = esm[i][tid];
            float e = expf(vv - vmax);
            denom += e;
            if (vv > bestv) { bestv = vv; bestl = sl[i]; }   // ascending -> first max
            esm[i][tid] = e;
        }
        float inv = 1.f / denom;
        for (int i = 0; i < cnt; i++)
            g_sc[b][i][s] = esm[i][tid] * inv;

        flowout[(b * 2 + 0) * Ls + s] = (float)(bestl >> 6) - (float)y;
        flowout[(b * 2 + 1) * Ls + s] = (float)(bestl & 63) - (float)x;
    } else {
        // generic correct fallback (spills v/e through g_sc)
        float vmax = (cnt < Ls) ? 0.f : -INFINITY;
        for (int i = 0; i < cnt; i++) {
            float vv = 10.f * boxsum_g(&g_corr[b][i][0], y, x);
            vmax = fmaxf(vmax, vv);
            g_sc[b][i][s] = vv;
        }
        float denom = (cnt < Ls) ? (float)(Ls - cnt) * expf(-vmax) : 0.f;
        float bestv = -INFINITY; int bestl = 0;
        for (int i = 0; i < cnt; i++) {
            float vv = g_sc[b][i][s];
            float e = expf(vv - vmax);
            denom += e;
            if (vv > bestv) { bestv = vv; bestl = g_list[b][i]; }
            g_sc[b][i][s] = e;
        }
        float inv = 1.f / denom;
        for (int i = 0; i < cnt; i++) g_sc[b][i][s] *= inv;
        flowout[(b * 2 + 0) * Ls + s] = (float)(bestl >> 6) - (float)y;
        flowout[(b * 2 + 1) * Ls + s] = (float)(bestl & 63) - (float)x;
    }
}

// ---------------------------------------------------------------------------
// K5: rec[c,y,x] = sum_{ph,pw} sum_i scores[i,(y+1-ph,x+1-pw)] * K[i,c*9+pp]
// Both the candidate kernels AND the needed 3 score rows are staged in shared
// in one cooperative MLP burst per chunk; inner loop is pure LDS+FMA.
// final = (rec*m/9)*m + fg*(1-m).  Block covers 4 consecutive s in ONE row.
// ---------------------------------------------------------------------------
__global__ void k_rec(const float* __restrict__ fgin, const float* __restrict__ mask,
                      float* __restrict__ att) {
    int b = blockIdx.y;
    int cnt = g_cnt[b];
    int tid = threadIdx.x;               // 256
    int s = blockIdx.x * 4 + (tid >> 6);
    int c = tid & 63;
    int y = s >> 6, x = s & 63;          // y identical across block
    float mv  = mask[b * Ls + s];
    float fgv = fgin[(b * NC + c) * Ls + s];

    __shared__ float sk[RCH][KD];        // 27KB
    __shared__ float ssc[RCH][3][64];    // 9KB

    float acc = 0.f;
    for (int c0 = 0; c0 < cnt; c0 += RCH) {
        int nchunk = min(RCH, cnt - c0);
        const float* src = &g_K[b][c0][0];
        for (int t = tid; t < nchunk * KD; t += 256)
            ((float*)sk)[t] = src[t];
        for (int t = tid; t < nchunk * 192; t += 256) {
            int i = t / 192, rem = t % 192;
            int r = rem >> 6, xx = rem & 63;
            int gy = y - 1 + r;
            ((float*)ssc)[t] = (gy >= 0 && gy < Hh) ? g_sc[b][c0 + i][gy * Ww + xx] : 0.f;
        }
        __syncthreads();
        for (int i = 0; i < nchunk; i++) {
            const float* ki = &sk[i][c * 9];
            #pragma unroll
            for (int ph = 0; ph < 3; ph++) {
                int r = 2 - ph;          // yy = y+1-ph -> shared row (yy-(y-1))
                #pragma unroll
                for (int pw = 0; pw < 3; pw++) {
                    int xx = x + 1 - pw;
                    if (xx >= 0 && xx < Ww)
                        acc += ssc[i][r][xx] * ki[ph * 3 + pw];
                }
            }
        }
        __syncthreads();
    }
    float rec = (acc * mv) / 9.f;
    att[(b * NC + c) * Ls + s] = rec * mv + fgv * (1.f - mv);
}

// ---------------------------------------------------------------------------
extern "C" void kernel_launch(void* const* d_in, const int* in_sizes, int n_in,
                              void* d_out, int out_size) {
    const float* fg   = (const float*)d_in[0];   // foreground [2,64,64,64]
    const float* bg   = (const float*)d_in[1];   // background [2,64,64,64]
    const float* mask = (const float*)d_in[2];   // mask       [2,1,64,64]
    float* att  = (float*)d_out;                 // attended   [2,64,64,64]
    float* flow = (float*)d_out + Bz * NC * Ls;  // flow       [2,2,64,64]

    k_scanbuild<<<Bz, 1024>>>(mask, bg);
    k_corr<<<dim3(16, 64, Bz), 256>>>(fg);
    k_soft<<<dim3(32, Bz), 128>>>(flow);
    k_rec<<<dim3(1024, Bz), 256>>>(fg, mask, att);
}

// round 4
// speedup vs baseline: 1.4201x; 1.1816x over previous
#include <cuda_runtime.h>
#include <math.h>

// Problem constants: b=2, nc=64, H=W=64
#define Bz 2
#define NC 64
#define Hh 64
#define Ww 64
#define Ls 4096          // H*W
#define KD 576           // nc * 3 * 3
#define EPSF 1e-7f
#define MAXC 24          // fast-path candidate capacity in k_soft
#define CCH 16           // k_corr candidate chunk
#define RCH 12           // k_rec  candidate chunk

// Scratch (worst-case cnt == Ls; actual data gives cnt ~ 12 per sample)
__device__ int   g_cnt[Bz];
__device__ int   g_list[Bz][Ls];
__device__ float g_K[Bz][Ls][KD];     // normalized bg patch rows (candidates only)
__device__ float g_corr[Bz][Ls][Ls];  // corr rows   (candidates only)
__device__ float g_sc[Bz][Ls][Ls];    // score rows  (candidates only)

// ---------------------------------------------------------------------------
// K1: per-sample, ONE 1024-thread block. Phase A: mm[l] + block scan ->
// ordered candidate list. Phase B: build normalized kernel rows (16 at a time).
// ---------------------------------------------------------------------------
__global__ void k_scanbuild(const float* __restrict__ mask,
                            const float* __restrict__ bgin) {
    int b = blockIdx.x;
    const float* m = mask + b * Ls;
    int tid = threadIdx.x, lane = tid & 31, warp = tid >> 5;
    __shared__ int   wsum[32];
    __shared__ int   s_list[Ls];      // 16KB
    __shared__ int   s_cnt;
    __shared__ float s_norm[32];

    // ---- Phase A: mm + single-pass scan (4 cells/thread) ----
    int ok[4]; int myc = 0;
    #pragma unroll
    for (int j = 0; j < 4; j++) {
        int l = tid * 4 + j;
        int y = l >> 6, x = l & 63;
        int o = 1;
        #pragma unroll
        for (int dy = -1; dy <= 1; dy++) {
            int yy = y + dy;
            if (yy < 0 || yy >= Hh) continue;
            #pragma unroll
            for (int dx = -1; dx <= 1; dx++) {
                int xx = x + dx;
                if (xx >= 0 && xx < Ww && m[yy * Ww + xx] != 0.0f) o = 0;
            }
        }
        ok[j] = o; myc += o;
    }
    int v = myc;
    #pragma unroll
    for (int off = 1; off < 32; off <<= 1) {
        int t = __shfl_up_sync(0xffffffffu, v, off);
        if (lane >= off) v += t;
    }
    if (lane == 31) wsum[warp] = v;
    __syncthreads();
    if (warp == 0) {
        int t = wsum[lane];
        #pragma unroll
        for (int off = 1; off < 32; off <<= 1) {
            int u = __shfl_up_sync(0xffffffffu, t, off);
            if (lane >= off) t += u;
        }
        wsum[lane] = t;
    }
    __syncthreads();
    int excl = (v - myc) + (warp > 0 ? wsum[warp - 1] : 0);
    #pragma unroll
    for (int j = 0; j < 4; j++)
        if (ok[j]) s_list[excl++] = tid * 4 + j;
    if (tid == 0) { s_cnt = wsum[31]; g_cnt[b] = wsum[31]; }
    __syncthreads();
    int cnt = s_cnt;
    for (int t = tid; t < cnt; t += 1024) g_list[b][t] = s_list[t];

    // ---- Phase B: build normalized kernels, 16 candidates at a time ----
    int grp = tid >> 6;     // 0..15
    int c   = tid & 63;     // channel
    for (int i0 = 0; i0 < cnt; i0 += 16) {
        int i = i0 + grp;
        bool act = (i < cnt);
        int l = act ? s_list[i] : 0;
        int y = l >> 6, x = l & 63;
        float pv[9]; float ss = 0.f;
        #pragma unroll
        for (int pp = 0; pp < 9; pp++) {
            int ph = pp / 3, pw = pp % 3;
            int yy = y + ph - 1, xx = x + pw - 1;
            float t = 0.f;
            if (yy >= 0 && yy < Hh && xx >= 0 && xx < Ww)
                t = bgin[(b * NC + c) * Ls + yy * Ww + xx] * (1.f - m[yy * Ww + xx]);
            t += EPSF;
            pv[pp] = t; ss += t * t;
        }
        #pragma unroll
        for (int o = 16; o > 0; o >>= 1) ss += __shfl_xor_sync(0xffffffffu, ss, o);
        if (lane == 0) s_norm[warp] = ss;
        __syncthreads();
        float norm = sqrtf(s_norm[grp * 2] + s_norm[grp * 2 + 1]);
        if (act) {
            #pragma unroll
            for (int pp = 0; pp < 9; pp++)
                g_K[b][i][c * 9 + pp] = pv[pp] / norm;
        }
        __syncthreads();
    }
}

// ---------------------------------------------------------------------------
// K2: corr[i][s] = <K_i, fg patch at s>.  Block = one spatial row y (64 x),
// 256 threads = 64 x * 4 candidate-groups.  fg rows staged in shared per
// 16-channel chunk; candidate kernels staged too; ki LDS are broadcasts.
// Grid (64, Bz).
// ---------------------------------------------------------------------------
__global__ void k_corr(const float* __restrict__ fgin) {
    int b = blockIdx.y;
    int cnt = g_cnt[b];
    int y = blockIdx.x;
    int tid = threadIdx.x;
    int x = tid & 63, ig = tid >> 6;     // ig in 0..3

    __shared__ float sfg[16][3][64];     // 12KB  rows y-1..y+1 for 16 channels
    __shared__ float skc[CCH][16 * 9];   // 9KB

    for (int c0 = 0; c0 < cnt; c0 += CCH) {
        int nchunk = min(CCH, cnt - c0);
        float acc[4];
        #pragma unroll
        for (int j = 0; j < 4; j++) acc[j] = 0.f;

        for (int ch0 = 0; ch0 < NC; ch0 += 16) {
            for (int t = tid; t < 16 * 3 * 64; t += 256) {
                int ch = t / 192, rem = t % 192;
                int r = rem >> 6, xx = rem & 63;
                int gy = y - 1 + r;
                sfg[ch][r][xx] = (gy >= 0 && gy < Hh)
                    ? fgin[(b * NC + ch0 + ch) * Ls + gy * Ww + xx] : 0.f;
            }
            for (int t = tid; t < nchunk * 144; t += 256) {
                int i = t / 144, k = t % 144;
                skc[i][k] = g_K[b][c0 + i][ch0 * 9 + k];
            }
            __syncthreads();

            for (int c16 = 0; c16 < 16; c16++) {
                float fv[9];
                #pragma unroll
                for (int dr = 0; dr < 3; dr++) {
                    #pragma unroll
                    for (int dx = -1; dx <= 1; dx++) {
                        int xx = x + dx;
                        fv[dr * 3 + dx + 1] = (xx >= 0 && xx < Ww) ? sfg[c16][dr][xx] : 0.f;
                    }
                }
                #pragma unroll
                for (int j = 0; j < 4; j++) {
                    int i = ig + j * 4;
                    if (i < nchunk) {
                        const float* kk = &skc[i][c16 * 9];
                        acc[j] += kk[0] * fv[0] + kk[1] * fv[1] + kk[2] * fv[2]
                                + kk[3] * fv[3] + kk[4] * fv[4] + kk[5] * fv[5]
                                + kk[6] * fv[6] + kk[7] * fv[7] + kk[8] * fv[8];
                    }
                }
            }
            __syncthreads();
        }
        #pragma unroll
        for (int j = 0; j < 4; j++) {
            int i = ig + j * 4;
            if (i < nchunk) g_corr[b][c0 + i][y * Ww + x] = acc[j];
        }
    }
}

// 3x3 spatial box-sum of a global corr row (zero outside grid) — slow path
__device__ __forceinline__ float boxsum_g(const float* __restrict__ row, int y, int x) {
    float a = 0.f;
    #pragma unroll
    for (int dy = -1; dy <= 1; dy++) {
        int yy = y + dy;
        if (yy < 0 || yy >= Hh) continue;
        const float* r = row + yy * Ww;
        #pragma unroll
        for (int dx = -1; dx <= 1; dx++) {
            int xx = x + dx;
            if (xx >= 0 && xx < Ww) a += r[xx];
        }
    }
    return a;
}

// ---------------------------------------------------------------------------
// K3: per spatial s: v_i = 10 * boxsum(corr_i); softmax over full l-axis
// (masked rows contribute exp(-vmax) each, closed-form); scores; argmax->flow.
// Fast path (cnt<=MAXC): ONE MLP burst loads all candidate rows into shared.
// Block: 128 threads = 2 spatial rows. Grid: (32, Bz).
// ---------------------------------------------------------------------------
__global__ void k_soft(float* __restrict__ flowout) {
    int b = blockIdx.y;
    int cnt = g_cnt[b];
    int tid = threadIdx.x;               // 0..127
    int r0 = blockIdx.x * 2;
    int q = tid >> 6, x = tid & 63;
    int y = r0 + q;
    int s = y * Ww + x;

    __shared__ float raw[MAXC][4][64];   // 24KB
    __shared__ float esm[MAXC][128];     // 12KB
    __shared__ int   sl[MAXC];

    if (cnt <= MAXC) {
        for (int i = 0; i < cnt; i++) {
            #pragma unroll
            for (int t2 = 0; t2 < 2; t2++) {
                int t = tid + t2 * 128;
                int j = t >> 6, xx = t & 63;
                int gr = r0 - 1 + j;
                raw[i][j][xx] = (gr >= 0 && gr < Hh) ? g_corr[b][i][gr * Ww + xx] : 0.f;
            }
        }
        if (tid < cnt) sl[tid] = g_list[b][tid];
        __syncthreads();

        float vmax = (cnt < Ls) ? 0.f : -INFINITY;
        for (int i = 0; i < cnt; i++) {
            float a = 0.f;
            #pragma unroll
            for (int dy = 0; dy < 3; dy++) {
                #pragma unroll
                for (int dx = -1; dx <= 1; dx++) {
                    int xx = x + dx;
                    if (xx >= 0 && xx < 64) a += raw[i][q + dy][xx];
                }
            }
            float vv = 10.f * a;
            esm[i][tid] = vv;
            vmax = fmaxf(vmax, vv);
        }
        float denom = (cnt < Ls) ? (float)(Ls - cnt) * expf(-vmax) : 0.f;
        float bestv = -INFINITY; int bestl = 0;
        for (int i = 0; i < cnt; i++) {
            float vv = esm[i][tid];
            float e = expf(vv - vmax);
            denom += e;
            if (vv > bestv) { bestv = vv; bestl = sl[i]; }   // ascending -> first max
            esm[i][tid] = e;
        }
        float inv = 1.f / denom;
        for (int i = 0; i < cnt; i++)
            g_sc[b][i][s] = esm[i][tid] * inv;

        flowout[(b * 2 + 0) * Ls + s] = (float)(bestl >> 6) - (float)y;
        flowout[(b * 2 + 1) * Ls + s] = (float)(bestl & 63) - (float)x;
    } else {
        float vmax = (cnt < Ls) ? 0.f : -INFINITY;
        for (int i = 0; i < cnt; i++) {
            float vv = 10.f * boxsum_g(&g_corr[b][i][0], y, x);
            vmax = fmaxf(vmax, vv);
            g_sc[b][i][s] = vv;
        }
        float denom = (cnt < Ls) ? (float)(Ls - cnt) * expf(-vmax) : 0.f;
        float bestv = -INFINITY; int bestl = 0;
        for (int i = 0; i < cnt; i++) {
            float vv = g_sc[b][i][s];
            float e = expf(vv - vmax);
            denom += e;
            if (vv > bestv) { bestv = vv; bestl = g_list[b][i]; }
            g_sc[b][i][s] = e;
        }
        float inv = 1.f / denom;
        for (int i = 0; i < cnt; i++) g_sc[b][i][s] *= inv;
        flowout[(b * 2 + 0) * Ls + s] = (float)(bestl >> 6) - (float)y;
        flowout[(b * 2 + 1) * Ls + s] = (float)(bestl & 63) - (float)x;
    }
}

// ---------------------------------------------------------------------------
// K4: rec[c,y,x] = sum_{ph,pw} sum_i scores[i,(y+1-ph,x+1-pw)] * K[i,c*9+pp]
// Block = one spatial row y. Thread = (x-group of 16, channel). Per candidate:
// ki[9] in regs (amortized over 16 outputs), 18-wide padded score window in
// regs per ph-row. final = (rec*m/9)*m + fg*(1-m).  Grid (64, Bz).
// ---------------------------------------------------------------------------
__global__ void k_rec(const float* __restrict__ fgin, const float* __restrict__ mask,
                      float* __restrict__ att) {
    int b = blockIdx.y;
    int cnt = g_cnt[b];
    int y = blockIdx.x;
    int tid = threadIdx.x;               // 256
    int g = tid >> 6, c = tid & 63;
    int xbase = g * 16;

    __shared__ float sk[RCH][KD];        // 27.6KB
    __shared__ float ssc[RCH][3][68];    // 9.8KB; col j holds score at x=j-1
    __shared__ float smask[64];

    if (tid < 64) smask[tid] = mask[b * Ls + y * Ww + tid];

    float acc[16];
    #pragma unroll
    for (int j = 0; j < 16; j++) acc[j] = 0.f;

    for (int c0 = 0; c0 < cnt; c0 += RCH) {
        int nchunk = min(RCH, cnt - c0);
        const float* ksrc = &g_K[b][c0][0];
        for (int t = tid; t < nchunk * KD; t += 256)
            ((float*)sk)[t] = ksrc[t];
        for (int t = tid; t < nchunk * 3 * 68; t += 256) {
            int i = t / 204, rem = t % 204;
            int r = rem / 68, j = rem % 68;
            int gy = y - 1 + r, xx = j - 1;
            float v = 0.f;
            if (gy >= 0 && gy < Hh && xx >= 0 && xx < Ww)
                v = g_sc[b][c0 + i][gy * Ww + xx];
            ssc[i][r][j] = v;
        }
        __syncthreads();

        for (int i = 0; i < nchunk; i++) {
            float ki[9];
            #pragma unroll
            for (int p = 0; p < 9; p++) ki[p] = sk[i][c * 9 + p];
            #pragma unroll
            for (int ph = 0; ph < 3; ph++) {
                const float* row = ssc[i][2 - ph];  // yy = y+1-ph
                float w[18];
                #pragma unroll
                for (int j = 0; j < 18; j++) w[j] = row[xbase + j];
                #pragma unroll
                for (int xo = 0; xo < 16; xo++)
                    acc[xo] += ki[ph * 3 + 0] * w[xo + 2]
                             + ki[ph * 3 + 1] * w[xo + 1]
                             + ki[ph * 3 + 2] * w[xo];
            }
        }
        __syncthreads();
    }

    const float* fgrow = fgin + (b * NC + c) * Ls + y * Ww + xbase;
    float* outrow      = att  + (b * NC + c) * Ls + y * Ww + xbase;
    #pragma unroll
    for (int xo = 0; xo < 16; xo++) {
        float mv  = smask[xbase + xo];
        float fgv = fgrow[xo];
        float rec = (acc[xo] * mv) / 9.f;
        outrow[xo] = rec * mv + fgv * (1.f - mv);
    }
}

// ---------------------------------------------------------------------------
extern "C" void kernel_launch(void* const* d_in, const int* in_sizes, int n_in,
                              void* d_out, int out_size) {
    const float* fg   = (const float*)d_in[0];   // foreground [2,64,64,64]
    const float* bg   = (const float*)d_in[1];   // background [2,64,64,64]
    const float* mask = (const float*)d_in[2];   // mask       [2,1,64,64]
    float* att  = (float*)d_out;                 // attended   [2,64,64,64]
    float* flow = (float*)d_out + Bz * NC * Ls;  // flow       [2,2,64,64]

    k_scanbuild<<<Bz, 1024>>>(mask, bg);
    k_corr<<<dim3(64, Bz), 256>>>(fg);
    k_soft<<<dim3(32, Bz), 128>>>(flow);
    k_rec<<<dim3(64, Bz), 256>>>(fg, mask, att);
}

// round 5
// speedup vs baseline: 1.7841x; 1.2563x over previous
#include <cuda_runtime.h>
#include <math.h>

// Problem constants: b=2, nc=64, H=W=64
#define Bz 2
#define NC 64
#define Hh 64
#define Ww 64
#define Ls 4096          // H*W
#define KD 576           // nc * 3 * 3
#define EPSF 1e-7f
#define MAXC 24          // fast-path candidate capacity in k_soft
#define CQ   3           // k_corr candidate chunk per block
#define RCH  12          // k_rec candidate chunk

// Scratch (worst-case cnt == Ls; actual data gives cnt ~ 12 per sample)
__device__ int   g_cnt[Bz];
__device__ int   g_list[Bz][Ls];
__device__ float g_K[Bz][Ls][KD];     // normalized bg patch rows (candidates only)
__device__ float g_corr[Bz][Ls][Ls];  // corr rows   (candidates only)
__device__ float g_sc[Bz][Ls][Ls];    // score rows  (candidates only)

// ---------------------------------------------------------------------------
// K1: per-sample, ONE 1024-thread block. Phase A: mm[l] + block scan ->
// ordered candidate list. Phase B: build normalized kernel rows (16 at a time).
// ---------------------------------------------------------------------------
__global__ void k_scanbuild(const float* __restrict__ mask,
                            const float* __restrict__ bgin) {
    int b = blockIdx.x;
    const float* m = mask + b * Ls;
    int tid = threadIdx.x, lane = tid & 31, warp = tid >> 5;
    __shared__ int   wsum[32];
    __shared__ int   s_list[Ls];      // 16KB
    __shared__ int   s_cnt;
    __shared__ float s_norm[32];

    int ok[4]; int myc = 0;
    #pragma unroll
    for (int j = 0; j < 4; j++) {
        int l = tid * 4 + j;
        int y = l >> 6, x = l & 63;
        int o = 1;
        #pragma unroll
        for (int dy = -1; dy <= 1; dy++) {
            int yy = y + dy;
            if (yy < 0 || yy >= Hh) continue;
            #pragma unroll
            for (int dx = -1; dx <= 1; dx++) {
                int xx = x + dx;
                if (xx >= 0 && xx < Ww && m[yy * Ww + xx] != 0.0f) o = 0;
            }
        }
        ok[j] = o; myc += o;
    }
    int v = myc;
    #pragma unroll
    for (int off = 1; off < 32; off <<= 1) {
        int t = __shfl_up_sync(0xffffffffu, v, off);
        if (lane >= off) v += t;
    }
    if (lane == 31) wsum[warp] = v;
    __syncthreads();
    if (warp == 0) {
        int t = wsum[lane];
        #pragma unroll
        for (int off = 1; off < 32; off <<= 1) {
            int u = __shfl_up_sync(0xffffffffu, t, off);
            if (lane >= off) t += u;
        }
        wsum[lane] = t;
    }
    __syncthreads();
    int excl = (v - myc) + (warp > 0 ? wsum[warp - 1] : 0);
    #pragma unroll
    for (int j = 0; j < 4; j++)
        if (ok[j]) s_list[excl++] = tid * 4 + j;
    if (tid == 0) { s_cnt = wsum[31]; g_cnt[b] = wsum[31]; }
    __syncthreads();
    int cnt = s_cnt;
    for (int t = tid; t < cnt; t += 1024) g_list[b][t] = s_list[t];

    // ---- Phase B: build normalized kernels, 16 candidates at a time ----
    int grp = tid >> 6;     // 0..15
    int c   = tid & 63;     // channel
    for (int i0 = 0; i0 < cnt; i0 += 16) {
        int i = i0 + grp;
        bool act = (i < cnt);
        int l = act ? s_list[i] : 0;
        int y = l >> 6, x = l & 63;
        float pv[9]; float ss = 0.f;
        #pragma unroll
        for (int pp = 0; pp < 9; pp++) {
            int ph = pp / 3, pw = pp % 3;
            int yy = y + ph - 1, xx = x + pw - 1;
            float t = 0.f;
            if (yy >= 0 && yy < Hh && xx >= 0 && xx < Ww)
                t = bgin[(b * NC + c) * Ls + yy * Ww + xx] * (1.f - m[yy * Ww + xx]);
            t += EPSF;
            pv[pp] = t; ss += t * t;
        }
        #pragma unroll
        for (int o = 16; o > 0; o >>= 1) ss += __shfl_xor_sync(0xffffffffu, ss, o);
        if (lane == 0) s_norm[warp] = ss;
        __syncthreads();
        float norm = sqrtf(s_norm[grp * 2] + s_norm[grp * 2 + 1]);
        if (act) {
            #pragma unroll
            for (int pp = 0; pp < 9; pp++)
                g_K[b][i][c * 9 + pp] = pv[pp] / norm;
        }
        __syncthreads();
    }
}

// ---------------------------------------------------------------------------
// K2: corr[i][s] = <K_i, fg patch at s>.
// Grid (64 y, 4 cand-quarter, Bz) = 512 blocks. Block handles up to
// ceil(cnt/4) candidates (in chunks of CQ=3), all channels (two 32-ch halves).
// Thread = (channel-pair cgi in 16, x-quad xq in 16): register-blocked
// acc[3 cand][4 x]; window via LDS128+LDS64. 16-way cross-cgi smem reduce.
// ---------------------------------------------------------------------------
__global__ void __launch_bounds__(256) k_corr(const float* __restrict__ fgin) {
    int b = blockIdx.z;
    int cnt = g_cnt[b];
    int y  = blockIdx.x;
    int iq = blockIdx.y;                 // 0..3
    int qq = (cnt + 3) >> 2;
    int ibeg = iq * qq, iend = min(ibeg + qq, cnt);
    if (ibeg >= iend) return;

    int tid = threadIdx.x;
    int cgi = tid >> 4;                  // 0..15 channel-pair group
    int xq  = tid & 15;                  // x quad
    int xbase = xq * 4;

    __shared__ float sfg[32][3][68];     // 25.5KB; col j holds fg x = j-1
    __shared__ float skc[CQ][KD];        // 6.9KB
    __shared__ float buf[16][193];       // 12.1KB

    for (int i0 = ibeg; i0 < iend; i0 += CQ) {
        int nch = min(CQ, iend - i0);
        float acc[CQ][4];
        #pragma unroll
        for (int j = 0; j < CQ; j++)
            #pragma unroll
            for (int xo = 0; xo < 4; xo++) acc[j][xo] = 0.f;

        // stage kernels for this chunk (float4)
        for (int t = tid; t < nch * (KD / 4); t += 256) {
            int i = t / (KD / 4), k = t % (KD / 4);
            ((float4*)skc[i])[k] = ((const float4*)&g_K[b][i0 + i][0])[k];
        }

        for (int half = 0; half < 2; half++) {
            // stage 32 channels x 3 rows, zero-padded cols 0 and 65..67
            for (int t = tid; t < 32 * 3 * 68; t += 256) {
                int ch = t / 204, rem = t % 204;
                int r = rem / 68, j = rem % 68;
                int gy = y - 1 + r;
                float v = 0.f;
                if (gy >= 0 && gy < Hh && j >= 1 && j <= 64)
                    v = fgin[(b * NC + half * 32 + ch) * Ls + gy * Ww + (j - 1)];
                sfg[ch][r][j] = v;
            }
            __syncthreads();

            #pragma unroll
            for (int c2 = 0; c2 < 2; c2++) {
                int ch = cgi * 2 + c2;
                int cglob = half * 32 + ch;
                float w[3][6];
                #pragma unroll
                for (int r = 0; r < 3; r++) {
                    float4 a = *(const float4*)&sfg[ch][r][xbase];
                    float2 e = *(const float2*)&sfg[ch][r][xbase + 4];
                    w[r][0] = a.x; w[r][1] = a.y; w[r][2] = a.z; w[r][3] = a.w;
                    w[r][4] = e.x; w[r][5] = e.y;
                }
                for (int j = 0; j < nch; j++) {
                    const float* kk = &skc[j][cglob * 9];
                    float k0 = kk[0], k1 = kk[1], k2 = kk[2];
                    float k3 = kk[3], k4 = kk[4], k5 = kk[5];
                    float k6 = kk[6], k7 = kk[7], k8 = kk[8];
                    #pragma unroll
                    for (int xo = 0; xo < 4; xo++) {
                        // fg index xx = x+dx -> col j2 = xo+dx+1
                        acc[j][xo] += k0 * w[0][xo]     + k1 * w[0][xo + 1] + k2 * w[0][xo + 2]
                                    + k3 * w[1][xo]     + k4 * w[1][xo + 1] + k5 * w[1][xo + 2]
                                    + k6 * w[2][xo]     + k7 * w[2][xo + 1] + k8 * w[2][xo + 2];
                    }
                }
            }
            __syncthreads();    // before restaging next half / reusing buf
        }

        // 16-way reduction across channel groups (fixed order, deterministic)
        for (int j = 0; j < nch; j++)
            #pragma unroll
            for (int xo = 0; xo < 4; xo++)
                buf[cgi][j * 64 + xbase + xo] = acc[j][xo];
        __syncthreads();
        if (tid < nch * 64) {
            float s = 0.f;
            #pragma unroll
            for (int g = 0; g < 16; g++) s += buf[g][tid];
            int j = tid >> 6, x = tid & 63;
            g_corr[b][i0 + j][y * Ww + x] = s;
        }
        __syncthreads();
    }
}

// 3x3 spatial box-sum of a global corr row (zero outside grid) — slow path
__device__ __forceinline__ float boxsum_g(const float* __restrict__ row, int y, int x) {
    float a = 0.f;
    #pragma unroll
    for (int dy = -1; dy <= 1; dy++) {
        int yy = y + dy;
        if (yy < 0 || yy >= Hh) continue;
        const float* r = row + yy * Ww;
        #pragma unroll
        for (int dx = -1; dx <= 1; dx++) {
            int xx = x + dx;
            if (xx >= 0 && xx < Ww) a += r[xx];
        }
    }
    return a;
}

// ---------------------------------------------------------------------------
// K3: per spatial s: v_i = 10 * boxsum(corr_i); softmax over full l-axis
// (masked rows contribute exp(-vmax) each, closed-form); scores; argmax->flow.
// Fast path (cnt<=MAXC): ONE MLP burst loads all candidate rows into shared.
// Block: 128 threads = 2 spatial rows. Grid: (32, Bz).
// ---------------------------------------------------------------------------
__global__ void k_soft(float* __restrict__ flowout) {
    int b = blockIdx.y;
    int cnt = g_cnt[b];
    int tid = threadIdx.x;               // 0..127
    int r0 = blockIdx.x * 2;
    int q = tid >> 6, x = tid & 63;
    int y = r0 + q;
    int s = y * Ww + x;

    __shared__ float raw[MAXC][4][64];   // 24KB
    __shared__ float esm[MAXC][128];     // 12KB
    __shared__ int   sl[MAXC];

    if (cnt <= MAXC) {
        for (int i = 0; i < cnt; i++) {
            #pragma unroll
            for (int t2 = 0; t2 < 2; t2++) {
                int t = tid + t2 * 128;
                int j = t >> 6, xx = t & 63;
                int gr = r0 - 1 + j;
                raw[i][j][xx] = (gr >= 0 && gr < Hh) ? g_corr[b][i][gr * Ww + xx] : 0.f;
            }
        }
        if (tid < cnt) sl[tid] = g_list[b][tid];
        __syncthreads();

        float vmax = (cnt < Ls) ? 0.f : -INFINITY;
        for (int i = 0; i < cnt; i++) {
            float a = 0.f;
            #pragma unroll
            for (int dy = 0; dy < 3; dy++) {
                #pragma unroll
                for (int dx = -1; dx <= 1; dx++) {
                    int xx = x + dx;
                    if (xx >= 0 && xx < 64) a += raw[i][q + dy][xx];
                }
            }
            float vv = 10.f * a;
            esm[i][tid] = vv;
            vmax = fmaxf(vmax, vv);
        }
        float denom = (cnt < Ls) ? (float)(Ls - cnt) * expf(-vmax) : 0.f;
        float bestv = -INFINITY; int bestl = 0;
        for (int i = 0; i < cnt; i++) {
            float vv = esm[i][tid];
            float e = expf(vv - vmax);
            denom += e;
            if (vv > bestv) { bestv = vv; bestl = sl[i]; }   // ascending -> first max
            esm[i][tid] = e;
        }
        float inv = 1.f / denom;
        for (int i = 0; i < cnt; i++)
            g_sc[b][i][s] = esm[i][tid] * inv;

        flowout[(b * 2 + 0) * Ls + s] = (float)(bestl >> 6) - (float)y;
        flowout[(b * 2 + 1) * Ls + s] = (float)(bestl & 63) - (float)x;
    } else {
        float vmax = (cnt < Ls) ? 0.f : -INFINITY;
        for (int i = 0; i < cnt; i++) {
            float vv = 10.f * boxsum_g(&g_corr[b][i][0], y, x);
            vmax = fmaxf(vmax, vv);
            g_sc[b][i][s] = vv;
        }
        float denom = (cnt < Ls) ? (float)(Ls - cnt) * expf(-vmax) : 0.f;
        float bestv = -INFINITY; int bestl = 0;
        for (int i = 0; i < cnt; i++) {
            float vv = g_sc[b][i][s];
            float e = expf(vv - vmax);
            denom += e;
            if (vv > bestv) { bestv = vv; bestl = g_list[b][i]; }
            g_sc[b][i][s] = e;
        }
        float inv = 1.f / denom;
        for (int i = 0; i < cnt; i++) g_sc[b][i][s] *= inv;
        flowout[(b * 2 + 0) * Ls + s] = (float)(bestl >> 6) - (float)y;
        flowout[(b * 2 + 1) * Ls + s] = (float)(bestl & 63) - (float)x;
    }
}

// ---------------------------------------------------------------------------
// K4: rec[c,y,x] = sum_{ph,pw} sum_i scores[i,(y+1-ph,x+1-pw)] * K[i,c*9+pp]
// Grid (64 y, 4 cg, Bz) = 512 blocks. Block handles 16 channels.
// Thread = (c16 in 16, x-quad xg in 16): ki[9] in regs per cand, window via
// LDS128+LDS64, acc[4]. final = (rec*m/9)*m + fg*(1-m), float4 store.
// ---------------------------------------------------------------------------
__global__ void __launch_bounds__(256) k_rec(const float* __restrict__ fgin,
                                             const float* __restrict__ mask,
                                             float* __restrict__ att) {
    int b = blockIdx.z, cg = blockIdx.y, y = blockIdx.x;
    int cnt = g_cnt[b];
    int tid = threadIdx.x;
    int c16 = tid >> 4, xg = tid & 15;
    int c = cg * 16 + c16;
    int xbase = xg * 4;

    __shared__ float sk[RCH][16 * 9];    // 6.9KB  (this cg's channel slice)
    __shared__ float ssc[RCH][3][72];    // 10.1KB; col j holds score x = j-1
    __shared__ float smask[64];

    if (tid < 64) smask[tid] = mask[b * Ls + y * Ww + tid];

    float acc[4] = {0.f, 0.f, 0.f, 0.f};

    for (int c0 = 0; c0 < cnt; c0 += RCH) {
        int nchunk = min(RCH, cnt - c0);
        for (int t = tid; t < nchunk * 144; t += 256) {
            int i = t / 144, k = t % 144;
            sk[i][k] = g_K[b][c0 + i][cg * 144 + k];
        }
        for (int t = tid; t < nchunk * 216; t += 256) {
            int i = t / 216, rem = t % 216;
            int r = rem / 72, j = rem % 72;
            int gy = y - 1 + r;
            float v = 0.f;
            if (gy >= 0 && gy < Hh && j >= 1 && j <= 64)
                v = g_sc[b][c0 + i][gy * Ww + (j - 1)];
            ssc[i][r][j] = v;
        }
        __syncthreads();

        for (int i = 0; i < nchunk; i++) {
            float ki[9];
            #pragma unroll
            for (int p = 0; p < 9; p++) ki[p] = sk[i][c16 * 9 + p];
            #pragma unroll
            for (int ph = 0; ph < 3; ph++) {
                const float* row = ssc[i][2 - ph];   // yy = y+1-ph
                float4 a = *(const float4*)&row[xbase];
                float2 e = *(const float2*)&row[xbase + 4];
                float w0 = a.x, w1 = a.y, w2 = a.z, w3 = a.w, w4 = e.x, w5 = e.y;
                // score col j = x+2-pw (col j holds x=j-1)
                acc[0] += ki[ph * 3 + 0] * w2 + ki[ph * 3 + 1] * w1 + ki[ph * 3 + 2] * w0;
                acc[1] += ki[ph * 3 + 0] * w3 + ki[ph * 3 + 1] * w2 + ki[ph * 3 + 2] * w1;
                acc[2] += ki[ph * 3 + 0] * w4 + ki[ph * 3 + 1] * w3 + ki[ph * 3 + 2] * w2;
                acc[3] += ki[ph * 3 + 0] * w5 + ki[ph * 3 + 1] * w4 + ki[ph * 3 + 2] * w3;
            }
        }
        __syncthreads();
    }

    const float* fgrow = fgin + (b * NC + c) * Ls + y * Ww + xbase;
    float4 fgv = *(const float4*)fgrow;
    float4 o;
    {
        float m0 = smask[xbase + 0], m1 = smask[xbase + 1];
        float m2 = smask[xbase + 2], m3 = smask[xbase + 3];
        o.x = ((acc[0] * m0) / 9.f) * m0 + fgv.x * (1.f - m0);
        o.y = ((acc[1] * m1) / 9.f) * m1 + fgv.y * (1.f - m1);
        o.z = ((acc[2] * m2) / 9.f) * m2 + fgv.z * (1.f - m2);
        o.w = ((acc[3] * m3) / 9.f) * m3 + fgv.w * (1.f - m3);
    }
    *(float4*)(att + (b * NC + c) * Ls + y * Ww + xbase) = o;
}

// ---------------------------------------------------------------------------
extern "C" void kernel_launch(void* const* d_in, const int* in_sizes, int n_in,
                              void* d_out, int out_size) {
    const float* fg   = (const float*)d_in[0];   // foreground [2,64,64,64]
    const float* bg   = (const float*)d_in[1];   // background [2,64,64,64]
    const float* mask = (const float*)d_in[2];   // mask       [2,1,64,64]
    float* att  = (float*)d_out;                 // attended   [2,64,64,64]
    float* flow = (float*)d_out + Bz * NC * Ls;  // flow       [2,2,64,64]

    k_scanbuild<<<Bz, 1024>>>(mask, bg);
    k_corr<<<dim3(64, 4, Bz), 256>>>(fg);
    k_soft<<<dim3(32, Bz), 128>>>(flow);
    k_rec<<<dim3(64, 4, Bz), 256>>>(fg, mask, att);
}